// round 1
// baseline (speedup 1.0000x reference)
#include <cuda_runtime.h>
#include <cuda_bf16.h>
#include <math.h>

// Problem constants (fixed by the reference):
//   B=8, T=256, U=64, V=1024
// Inputs (metadata order = setup_inputs dict order):
//   d_in[0] = logits      float32  [B, T, U, V]
//   d_in[1] = ys          int32    [B, U]        (unused)
//   d_in[2] = soft_labels float32  [B, U, V]
//   d_in[3] = aligns      int32    [B, U]
//   d_in[4] = xlens       int32    [B]           (unused)
//   d_in[5] = ylens       int32    [B]
// Output: scalar float32 loss.
//
// Only B rows of V floats are ever touched: logits[b, aligns[b,u], u, :] with
// u = ylens[b]-1. One CTA, 1024 threads, 128 threads per batch element.

#define B_ 8
#define T_ 256
#define U_ 64
#define V_ 1024
#define GROUP_THREADS 128          // threads per batch element
#define ELEMS_PER_THREAD (V_ / GROUP_THREADS)   // 8

__device__ __forceinline__ float warp_reduce_max(float v) {
    #pragma unroll
    for (int off = 16; off > 0; off >>= 1)
        v = fmaxf(v, __shfl_xor_sync(0xFFFFFFFFu, v, off));
    return v;
}
__device__ __forceinline__ float warp_reduce_sum(float v) {
    #pragma unroll
    for (int off = 16; off > 0; off >>= 1)
        v += __shfl_xor_sync(0xFFFFFFFFu, v, off);
    return v;
}

__global__ __launch_bounds__(1024, 1)
void rnnt_align_distill_loss_kernel(const float* __restrict__ logits,
                                    const float* __restrict__ soft_labels,
                                    const int*   __restrict__ aligns,
                                    const int*   __restrict__ ylens,
                                    float*       __restrict__ out)
{
    const int tid  = threadIdx.x;        // 0..1023
    const int b    = tid >> 7;           // batch element for this group (0..7)
    const int lt   = tid & (GROUP_THREADS - 1);   // 0..127 within group
    const int warp_in_group = lt >> 5;   // 0..3
    const int lane = lt & 31;

    // Per-group scratch: [B][4 warps] for cross-warp reduction, plus [B] result.
    __shared__ float sm_red[B_][4];
    __shared__ float sm_loss[B_];

    // --- gather indices -----------------------------------------------------
    const int ylen = ylens[b];
    const int u    = ylen - 1;
    const int t    = aligns[b * U_ + u];

    const float* sel = logits      + (((size_t)b * T_ + t) * U_ + u) * V_;
    const float* sl  = soft_labels + ((size_t)b * U_ + u) * V_;

    // --- load 8 logits + 8 soft labels per thread ---------------------------
    float x[ELEMS_PER_THREAD];
    float s[ELEMS_PER_THREAD];
    #pragma unroll
    for (int k = 0; k < ELEMS_PER_THREAD; k++) {
        const int idx = lt + k * GROUP_THREADS;
        x[k] = sel[idx];
        s[k] = sl[idx];
    }

    // --- phase 1: max over V ------------------------------------------------
    float mx = -INFINITY;
    #pragma unroll
    for (int k = 0; k < ELEMS_PER_THREAD; k++) mx = fmaxf(mx, x[k]);
    mx = warp_reduce_max(mx);
    if (lane == 0) sm_red[b][warp_in_group] = mx;
    __syncthreads();
    mx = fmaxf(fmaxf(sm_red[b][0], sm_red[b][1]),
               fmaxf(sm_red[b][2], sm_red[b][3]));
    __syncthreads();   // protect sm_red for reuse

    // --- phase 2: sum exp(x - mx) -------------------------------------------
    float se = 0.0f;
    #pragma unroll
    for (int k = 0; k < ELEMS_PER_THREAD; k++) se += __expf(x[k] - mx);
    se = warp_reduce_sum(se);
    if (lane == 0) sm_red[b][warp_in_group] = se;
    __syncthreads();
    se = sm_red[b][0] + sm_red[b][1] + sm_red[b][2] + sm_red[b][3];
    const float lse = mx + __logf(se);
    __syncthreads();   // protect sm_red for reuse

    // --- phase 3: dot(soft_labels, logp) ------------------------------------
    float dot = 0.0f;
    #pragma unroll
    for (int k = 0; k < ELEMS_PER_THREAD; k++) dot += s[k] * (x[k] - lse);
    dot = warp_reduce_sum(dot);
    if (lane == 0) sm_red[b][warp_in_group] = dot;
    __syncthreads();
    if (lt == 0) {
        const float loss_u = (sm_red[b][0] + sm_red[b][1] +
                              sm_red[b][2] + sm_red[b][3]) / (float)ylen;
        sm_loss[b] = loss_u;
    }
    __syncthreads();

    // --- final: -sum_b(loss_u_b) / B ----------------------------------------
    if (tid == 0) {
        float total = 0.0f;
        #pragma unroll
        for (int bb = 0; bb < B_; bb++) total += sm_loss[bb];
        out[0] = -total / (float)B_;
    }
}

extern "C" void kernel_launch(void* const* d_in, const int* in_sizes, int n_in,
                              void* d_out, int out_size)
{
    const float* logits      = (const float*)d_in[0];
    const float* soft_labels = (const float*)d_in[2];
    const int*   aligns      = (const int*)d_in[3];
    const int*   ylens       = (const int*)d_in[5];
    float*       out         = (float*)d_out;

    rnnt_align_distill_loss_kernel<<<1, 1024>>>(logits, soft_labels, aligns, ylens, out);
}

// round 2
// speedup vs baseline: 1.0147x; 1.0147x over previous
#include <cuda_runtime.h>
#include <cuda_bf16.h>
#include <math.h>

// RNNTAlignDistillLoss — B=8, T=256, U=64, V=1024.
// Inputs: d_in[0]=logits f32[B,T,U,V], d_in[1]=ys (unused),
//         d_in[2]=soft_labels f32[B,U,V], d_in[3]=aligns i32[B,U],
//         d_in[4]=xlens (unused), d_in[5]=ylens i32[B].
// Output: scalar f32.
//
// Only 8 rows of 1024 floats are live. One CTA, 8 warps, warp b handles
// batch element b. Index chain shortened to depth 2 by speculatively
// loading the full aligns row alongside ylens. Single fused reduction:
// loss_b = (Σ s·x − log(Σ e^x)) / ylen   (valid since Σs = 1 over full V).

#define B_ 8
#define T_ 256
#define U_ 64
#define V_ 1024

__global__ __launch_bounds__(256, 1)
void rnnt_align_distill_loss_kernel(const float* __restrict__ logits,
                                    const float* __restrict__ soft_labels,
                                    const int*   __restrict__ aligns,
                                    const int*   __restrict__ ylens,
                                    float*       __restrict__ out)
{
    const int b    = threadIdx.x >> 5;   // warp id = batch element (0..7)
    const int lane = threadIdx.x & 31;

    __shared__ float sm_loss[B_];

    // --- two independent index loads (issue back-to-back, overlap) ----------
    const int  ylen = ylens[b];                                  // dep load 1
    const int2 arow = ((const int2*)(aligns + b * U_))[lane];    // full row, parallel

    const int u  = ylen - 1;
    // select t = aligns[b][u] from the distributed row via shuffle
    const int sx = __shfl_sync(0xFFFFFFFFu, arow.x, u >> 1);
    const int sy = __shfl_sync(0xFFFFFFFFu, arow.y, u >> 1);
    const int t  = (u & 1) ? sy : sx;

    const float4* sel = (const float4*)(logits +
                        (((size_t)b * T_ + t) * U_ + u) * V_);
    const float4* sl  = (const float4*)(soft_labels +
                        ((size_t)b * U_ + u) * V_);

    // --- single fused pass: sum-exp and soft-label dot ----------------------
    float se  = 0.0f;   // Σ exp(x)
    float dot = 0.0f;   // Σ s·x
    #pragma unroll
    for (int k = 0; k < 8; k++) {
        const float4 x = sel[lane + k * 32];
        const float4 s = sl [lane + k * 32];
        se  += __expf(x.x) + __expf(x.y) + __expf(x.z) + __expf(x.w);
        dot += s.x * x.x + s.y * x.y + s.z * x.z + s.w * x.w;
    }

    // --- one warp reduction for both scalars --------------------------------
    #pragma unroll
    for (int off = 16; off > 0; off >>= 1) {
        se  += __shfl_xor_sync(0xFFFFFFFFu, se,  off);
        dot += __shfl_xor_sync(0xFFFFFFFFu, dot, off);
    }

    if (lane == 0)
        sm_loss[b] = (dot - __logf(se)) / (float)ylen;
    __syncthreads();

    if (threadIdx.x == 0) {
        float total = 0.0f;
        #pragma unroll
        for (int bb = 0; bb < B_; bb++) total += sm_loss[bb];
        out[0] = -total * (1.0f / (float)B_);
    }
}

extern "C" void kernel_launch(void* const* d_in, const int* in_sizes, int n_in,
                              void* d_out, int out_size)
{
    const float* logits      = (const float*)d_in[0];
    const float* soft_labels = (const float*)d_in[2];
    const int*   aligns      = (const int*)d_in[3];
    const int*   ylens       = (const int*)d_in[5];
    float*       out         = (float*)d_out;

    rnnt_align_distill_loss_kernel<<<1, 256>>>(logits, soft_labels, aligns, ylens, out);
}